// round 3
// baseline (speedup 1.0000x reference)
#include <cuda_runtime.h>

#define POOL      7
#define NUM_ROIS  300
#define FH        200
#define FW        200
#define FC        512
#define FC4       (FC / 4)   // 128 float4 per pixel

// One block per (cell, roi). 64 threads; thread t owns float4 slots t and t+64.
// 8 independent LDG.128 in flight per thread before any use.
__global__ __launch_bounds__(64)
void roi_pool_kernel(const float4* __restrict__ feat,
                     const int*    __restrict__ rois,
                     float4*       __restrict__ out)
{
    const int cell = blockIdx.x;          // 0..48
    const int roi  = blockIdx.y;          // 0..299
    const int py   = cell / POOL;
    const int px   = cell % POOL;
    const int t    = threadIdx.x;         // 0..63

    const int x0 = rois[roi * 4 + 0];
    const int y0 = rois[roi * 4 + 1];
    const int w  = rois[roi * 4 + 2];
    const int h  = rois[roi * 4 + 3];

    // Exact reference arithmetic
    const float hs = (float)h / (float)POOL;
    const float ws = (float)w / (float)POOL;
    const float sy = (float)py * hs;
    const float sx = (float)px * ws;

    const int y_lo = (int)floorf(sy);
    const int x_lo = (int)floorf(sx);
    const int y_hi = min(y_lo + 1, h - 1);
    const int x_hi = min(x_lo + 1, w - 1);

    const float fy = sy - (float)y_lo;
    const float fx = sx - (float)x_lo;
    const float gy = 1.0f - fy;
    const float gx = 1.0f - fx;

    const float w00 = gy * gx;
    const float w01 = gy * fx;
    const float w10 = fy * gx;
    const float w11 = fy * fx;

    const float4* __restrict__ p00 = feat + ((size_t)(y0 + y_lo) * FW + (x0 + x_lo)) * FC4;
    const float4* __restrict__ p01 = feat + ((size_t)(y0 + y_lo) * FW + (x0 + x_hi)) * FC4;
    const float4* __restrict__ p10 = feat + ((size_t)(y0 + y_hi) * FW + (x0 + x_lo)) * FC4;
    const float4* __restrict__ p11 = feat + ((size_t)(y0 + y_hi) * FW + (x0 + x_hi)) * FC4;

    float4* __restrict__ po = out + ((size_t)roi * (POOL * POOL) + cell) * FC4;

    const int ta = t;
    const int tb = t + 64;

    // Issue all 8 loads before any consumption (MLP = 8)
    const float4 a00 = p00[ta];
    const float4 a01 = p01[ta];
    const float4 a10 = p10[ta];
    const float4 a11 = p11[ta];
    const float4 b00 = p00[tb];
    const float4 b01 = p01[tb];
    const float4 b10 = p10[tb];
    const float4 b11 = p11[tb];

    float4 ra, rb;
    ra.x = w00 * a00.x + w01 * a01.x + w10 * a10.x + w11 * a11.x;
    ra.y = w00 * a00.y + w01 * a01.y + w10 * a10.y + w11 * a11.y;
    ra.z = w00 * a00.z + w01 * a01.z + w10 * a10.z + w11 * a11.z;
    ra.w = w00 * a00.w + w01 * a01.w + w10 * a10.w + w11 * a11.w;

    rb.x = w00 * b00.x + w01 * b01.x + w10 * b10.x + w11 * b11.x;
    rb.y = w00 * b00.y + w01 * b01.y + w10 * b10.y + w11 * b11.y;
    rb.z = w00 * b00.z + w01 * b01.z + w10 * b10.z + w11 * b11.z;
    rb.w = w00 * b00.w + w01 * b01.w + w10 * b10.w + w11 * b11.w;

    // Streaming stores: output is never re-read; keep it out of L2's way.
    __stcs(po + ta, ra);
    __stcs(po + tb, rb);
}

extern "C" void kernel_launch(void* const* d_in, const int* in_sizes, int n_in,
                              void* d_out, int out_size)
{
    const float4* feat = (const float4*)d_in[0];   // (1,200,200,512) f32
    const int*    rois = (const int*)d_in[1];      // (1,300,4) i32
    float4*       out  = (float4*)d_out;           // (1,300,7,7,512) f32

    dim3 grid(POOL * POOL, NUM_ROIS);
    roi_pool_kernel<<<grid, 64>>>(feat, rois, out);
}